// round 16
// baseline (speedup 1.0000x reference)
#include <cuda_runtime.h>
#include <cstdint>

// Problem constants
#define BB  16
#define NN  16384
#define SS  1024
#define CC  128
#define SEM 20

// Cluster FPS config
#define CL   4               // CTAs per cluster (one cluster per batch)
#define T    512             // threads per CTA
#define NLOC (NN / CL)       // 4096 points per CTA
#define PPT  (NLOC / T)      // 8 points per thread
#define NPAIR (PPT / 2)      // 4 packed pairs per thread
#define NW   (T / 32)        // 16 warps

#define A0 (BB * SS * 3)
#define A1 (BB * CC * SS)
#define A2 (BB * SS)

__device__ int g_idx[BB * SS];

// Dynamic smem layout (bytes)
#define OFF_X    0
#define OFF_Y    (NLOC * 4)
#define OFF_Z    (NLOC * 8)
#define OFF_CNT  (NLOC * 12)            // 32 floats
#define OFF_WARP (OFF_CNT + 128)        // 2 bufs x 16 x u64 {score, idx}
#define OFF_CAND (OFF_WARP + 256)       // [2 parity][4 slots][24B records]
#define SMEM_BYTES (OFF_CAND + 192)

// ---------------- PTX helpers ----------------
static __device__ __forceinline__ uint32_t smem_u32(const void* p) {
    uint32_t a;
    asm("{ .reg .u64 t; cvta.to.shared.u64 t, %1; cvt.u32.u64 %0, t; }"
        : "=r"(a) : "l"(p));
    return a;
}
static __device__ __forceinline__ uint32_t mapa_u32(uint32_t a, uint32_t rank) {
    uint32_t d;
    asm("mapa.shared::cluster.u32 %0, %1, %2;" : "=r"(d) : "r"(a), "r"(rank));
    return d;
}
static __device__ __forceinline__ void st_cl_u64(uint32_t a, uint64_t v) {
    asm volatile("st.shared::cluster.b64 [%0], %1;" :: "r"(a), "l"(v) : "memory");
}
static __device__ __forceinline__ void st_cl_rel_u64(uint32_t a, uint64_t v) {
    asm volatile("st.release.cluster.shared::cluster.b64 [%0], %1;"
                 :: "r"(a), "l"(v) : "memory");
}
static __device__ __forceinline__ void st_u64(uint32_t a, uint64_t v) {
    asm volatile("st.shared.b64 [%0], %1;" :: "r"(a), "l"(v) : "memory");
}
static __device__ __forceinline__ void st_rel_cta_u64(uint32_t a, uint64_t v) {
    asm volatile("st.release.cta.shared::cta.b64 [%0], %1;"
                 :: "r"(a), "l"(v) : "memory");
}
static __device__ __forceinline__ uint32_t ld_acq_cluster_u32(uint32_t a) {
    uint32_t v;
    asm volatile("ld.acquire.cluster.shared::cta.b32 %0, [%1];"
                 : "=r"(v) : "r"(a) : "memory");
    return v;
}
static __device__ __forceinline__ uint32_t ld_acq_cta_u32(uint32_t a) {
    uint32_t v;
    asm volatile("ld.acquire.cta.shared::cta.b32 %0, [%1];"
                 : "=r"(v) : "r"(a) : "memory");
    return v;
}
static __device__ __forceinline__ uint32_t redux_max_u32(uint32_t v) {
    uint32_t o;
    asm volatile("redux.sync.max.u32 %0, %1, 0xffffffff;" : "=r"(o) : "r"(v));
    return o;
}
// Packed f32x2 (per-lane bitwise identical to scalar rn ops)
static __device__ __forceinline__ uint64_t pk2(float lo, float hi) {
    uint64_t r;
    asm("mov.b64 %0, {%1, %2};"
        : "=l"(r) : "r"(__float_as_uint(lo)), "r"(__float_as_uint(hi)));
    return r;
}
static __device__ __forceinline__ void unpk2(uint64_t v, float& lo, float& hi) {
    uint32_t a, c;
    asm("mov.b64 {%0, %1}, %2;" : "=r"(a), "=r"(c) : "l"(v));
    lo = __uint_as_float(a); hi = __uint_as_float(c);
}
static __device__ __forceinline__ uint64_t add2(uint64_t a, uint64_t b) {
    uint64_t o; asm("add.rn.f32x2 %0, %1, %2;" : "=l"(o) : "l"(a), "l"(b)); return o;
}
static __device__ __forceinline__ uint64_t mul2(uint64_t a, uint64_t b) {
    uint64_t o; asm("mul.rn.f32x2 %0, %1, %2;" : "=l"(o) : "l"(a), "l"(b)); return o;
}
static __device__ __forceinline__ uint64_t fma2(uint64_t a, uint64_t b, uint64_t c) {
    uint64_t o; asm("fma.rn.f32x2 %0, %1, %2, %3;" : "=l"(o) : "l"(a), "l"(b), "l"(c)); return o;
}

// ---------------- FPS: one 4-CTA cluster per batch ----------------
__global__ __launch_bounds__(T, 1) __cluster_dims__(CL, 1, 1)
void fps_kernel(const float* __restrict__ xyz, const int* __restrict__ label)
{
    extern __shared__ char smem[];
    float* s_x   = (float*)(smem + OFF_X);
    float* s_y   = (float*)(smem + OFF_Y);
    float* s_z   = (float*)(smem + OFF_Z);
    float* s_cnt = (float*)(smem + OFF_CNT);
    unsigned long long* s_warp = (unsigned long long*)(smem + OFF_WARP);
    uint32_t* s_cand = (uint32_t*)(smem + OFF_CAND);  // [par][slot][6]: sc,gi,x,y,z,seq

    const int b    = blockIdx.x / CL;
    const int rank = blockIdx.x % CL;
    const int tid  = threadIdx.x;
    const int base = rank * NLOC;
    const float* bx = xyz + (size_t)b * NN * 3;
    const int*   bl = label + (size_t)b * NN;

    const uint32_t cand_a = smem_u32(s_cand);

    if (tid < 32) s_cnt[tid] = 0.0f;
    if (tid < 48) s_cand[tid] = 0u;      // all seq words 0; s >= 1
    __syncthreads();

    // Class histogram over the FULL batch + stage this CTA's coord shard.
    for (int i = tid; i < NN; i += T) atomicAdd(&s_cnt[bl[i]], 1.0f);
    for (int i = tid; i < NLOC; i += T) {
        int g = base + i;
        s_x[i] = bx[3 * g + 0];
        s_y[i] = bx[3 * g + 1];
        s_z[i] = bx[3 * g + 2];
    }
    __syncthreads();

    // Register-resident packed coords/weights. Pair j holds points
    // p0 = tid + (2j)*T, p1 = tid + (2j+1)*T.
    uint64_t px[NPAIR], py[NPAIR], pz[NPAIR], pw[NPAIR];
    float M[PPT];
    #pragma unroll
    for (int j = 0; j < NPAIR; j++) {
        int p0 = tid + (2 * j) * T, p1 = tid + (2 * j + 1) * T;
        px[j] = pk2(s_x[p0], s_x[p1]);
        py[j] = pk2(s_y[p0], s_y[p1]);
        pz[j] = pk2(s_z[p0], s_z[p1]);
        float w0 = s_cnt[bl[base + p0]], w1 = s_cnt[bl[base + p1]];
        pw[j] = pk2(w0, w1);
        M[2 * j]     = 1e10f * w0;      // matches min(1e10,d)*w after iter 1
        M[2 * j + 1] = 1e10f * w1;
    }

    float cx = bx[0], cy = bx[1], cz = bx[2];
    if (rank == 0 && tid == 0) g_idx[b * SS] = 0;

    const int wid = tid >> 5, lane = tid & 31;

    // Remote record destinations: warp-0 lanes 0..2 each serve one peer.
    // Record written into the RECEIVER's buffer at slot index == MY rank.
    uint32_t dst0 = 0, dst1 = 0;
    if (wid == 0 && lane < CL - 1) {
        uint32_t peer = (uint32_t)((rank + 1 + lane) % CL);
        dst0 = mapa_u32(cand_a + (uint32_t)(rank * 24),            peer);
        dst1 = mapa_u32(cand_a + (uint32_t)((CL + rank) * 24),     peer);
    }

    // Peers' smem must be initialized before any cross-CTA store.
    asm volatile("barrier.cluster.arrive.aligned;" ::: "memory");
    asm volatile("barrier.cluster.wait.aligned;" ::: "memory");

    for (int s = 1; s < SS; s++) {
        const uint64_t ncx = pk2(-cx, -cx);
        const uint64_t ncy = pk2(-cy, -cy);
        const uint64_t ncz = pk2(-cz, -cz);

        // ---- Phase 1: packed distance + min update; track max score ----
        float best = 0.0f;                       // scores >= 0
        #pragma unroll
        for (int j = 0; j < NPAIR; j++) {
            uint64_t dx = add2(px[j], ncx);      // rn(x - cx) per lane
            uint64_t dy = add2(py[j], ncy);
            uint64_t dz = add2(pz[j], ncz);
            uint64_t t  = mul2(dx, dx);          // XLA-contracted:
            t = fma2(dy, dy, t);                 // fma(dy,dy, dx*dx)
            t = fma2(dz, dz, t);                 // fma(dz,dz, ...)
            uint64_t dw = mul2(t, pw[j]);        // d * w
            float lo, hi; unpk2(dw, lo, hi);
            float m0 = fminf(M[2 * j],     lo);
            float m1 = fminf(M[2 * j + 1], hi);
            M[2 * j] = m0; M[2 * j + 1] = m1;
            best = fmaxf(best, m0);
            best = fmaxf(best, m1);
        }
        // ---- Phase 2: lowest local index attaining this thread's best ----
        int bi = 0x7fffffff;
        #pragma unroll
        for (int k = PPT - 1; k >= 0; k--)
            if (M[k] == best) bi = tid + k * T;

        // ---- Warp reduce (u32 max on non-negative score bits; min idx) ----
        uint32_t sb  = __float_as_uint(best);
        uint32_t smx = redux_max_u32(sb);
        unsigned bio = __reduce_min_sync(0xffffffffu,
                         (sb == smx) ? (unsigned)bi : 0x7fffffffu);
        unsigned long long* swb = &s_warp[(s & 1) * NW];   // parity buffered
        if (lane == 0)
            swb[wid] = (((unsigned long long)smx) << 32) | (unsigned long long)bio;
        __syncthreads();   // the ONLY barrier in the iteration

        const uint32_t bufw = (uint32_t)((s & 1) * CL * 6);  // parity buf (words)

        // ---- Warp 0 ONLY: CTA reduce, winner lookup, sends + own-slot write
        if (wid == 0) {
            unsigned long long pkd = (lane < NW) ? swb[lane] : 0ULL;
            uint32_t sc = (uint32_t)(pkd >> 32);
            uint32_t li = (lane < NW) ? (uint32_t)pkd : 0x7fffffffu;
            uint32_t cmax = redux_max_u32(sc);
            uint32_t lmin = __reduce_min_sync(0xffffffffu,
                              (sc == cmax) ? li : 0x7fffffffu);
            int   gi  = base + (int)lmin;
            float wxx = s_x[lmin], wyy = s_y[lmin], wzz = s_z[lmin];

            uint64_t r0 = ((uint64_t)(uint32_t)gi << 32) | (uint64_t)cmax;
            uint64_t r1 = ((uint64_t)__float_as_uint(wyy) << 32)
                        | (uint64_t)__float_as_uint(wxx);
            uint64_t r2 = ((uint64_t)(uint32_t)s << 32)
                        | (uint64_t)__float_as_uint(wzz);

            if (lane < CL - 1) {
                // lanes 0..2 send to the 3 peers in parallel
                uint32_t dst = (s & 1) ? dst1 : dst0;
                st_cl_u64(dst + 0, r0);
                st_cl_u64(dst + 8, r1);
                st_cl_rel_u64(dst + 16, r2);     // release: record visible
            } else if (lane == CL - 1) {
                // lane 3 publishes own CTA's record locally
                uint32_t own = cand_a + (bufw + (uint32_t)rank * 6) * 4;
                st_u64(own + 0, r0);
                st_u64(own + 8, r1);
                st_rel_cta_u64(own + 16, r2);    // release to own CTA
            }
        }

        // ---- ALL warps: poll 4 slots (own via cta-acquire, peers via
        //      cluster-acquire), compare 4 records in slot order ----
        uint32_t Wsc = 0u; int Wgi = 0x7fffffff;
        float Wx = cx, Wy = cy, Wz = cz;
        #pragma unroll
        for (int r = 0; r < CL; r++) {
            uint32_t wo    = bufw + (uint32_t)r * 6;
            uint32_t seq_a = cand_a + (wo + 5) * 4;
            if (r == rank) {
                while (ld_acq_cta_u32(seq_a) != (uint32_t)s) { }
            } else {
                while (ld_acq_cluster_u32(seq_a) != (uint32_t)s) { }
            }
            uint32_t psc = s_cand[wo + 0];
            int      pgi = (int)s_cand[wo + 1];
            // gi is monotone in r, so strict > keeps min-gi on ties.
            if (psc > Wsc) {
                Wsc = psc; Wgi = pgi;
                Wx = __uint_as_float(s_cand[wo + 2]);
                Wy = __uint_as_float(s_cand[wo + 3]);
                Wz = __uint_as_float(s_cand[wo + 4]);
            }
        }
        cx = Wx; cy = Wy; cz = Wz;
        if (rank == 0 && wid == 0 && lane == 0) g_idx[b * SS + s] = Wgi;
    }

    // Keep cluster alive until all remote traffic has retired.
    asm volatile("barrier.cluster.arrive.aligned;" ::: "memory");
    asm volatile("barrier.cluster.wait.aligned;" ::: "memory");
}

// ---------------- Gather ----------------
__global__ void gather_kernel(const float* __restrict__ xyz,
                              const float* __restrict__ feat,
                              const int*   __restrict__ label,
                              float* __restrict__ out)
{
    int i = blockIdx.x * blockDim.x + threadIdx.x;
    const int total = A0 + A1 + A2;
    if (i >= total) return;

    if (i < A0) {
        int b = i / (SS * 3);
        int r = i - b * SS * 3;
        int s = r / 3;
        int d = r - s * 3;
        int id = g_idx[b * SS + s];
        out[i] = xyz[((size_t)b * NN + id) * 3 + d];
    } else if (i < A0 + A1) {
        int j = i - A0;
        int b = j / (CC * SS);
        int r = j - b * CC * SS;
        int c = r / SS;
        int s = r - c * SS;
        int id = g_idx[b * SS + s];
        out[i] = feat[((size_t)b * CC + c) * NN + id];
    } else {
        int j = i - A0 - A1;
        int b = j / SS;
        int s = j - b * SS;
        int id = g_idx[b * SS + s];
        out[i] = (float)label[(size_t)b * NN + id];
    }
}

extern "C" void kernel_launch(void* const* d_in, const int* in_sizes, int n_in,
                              void* d_out, int out_size)
{
    const float* xyz   = (const float*)d_in[0];
    const float* feat  = (const float*)d_in[1];
    const int*   label = (const int*)  d_in[2];
    float*       out   = (float*)d_out;

    cudaFuncSetAttribute(fps_kernel,
                         cudaFuncAttributeMaxDynamicSharedMemorySize,
                         SMEM_BYTES);

    fps_kernel<<<BB * CL, T, SMEM_BYTES>>>(xyz, label);

    const int total = A0 + A1 + A2;
    gather_kernel<<<(total + 255) / 256, 256>>>(xyz, feat, label, out);
}

// round 17
// speedup vs baseline: 1.2146x; 1.2146x over previous
#include <cuda_runtime.h>
#include <cstdint>

// Problem constants
#define BB  16
#define NN  16384
#define SS  1024
#define CC  128
#define SEM 20

// Cluster FPS config
#define CL   4               // CTAs per cluster (one cluster per batch)
#define T    512             // threads per CTA
#define NLOC (NN / CL)       // 4096 points per CTA
#define PPT  (NLOC / T)      // 8 points per thread
#define NPAIR (PPT / 2)      // 4 packed pairs per thread
#define NW   (T / 32)        // 16 warps

#define A0 (BB * SS * 3)
#define A1 (BB * CC * SS)
#define A2 (BB * SS)

__device__ int g_idx[BB * SS];

// Dynamic smem layout (bytes)
#define OFF_X    0
#define OFF_Y    (NLOC * 4)
#define OFF_Z    (NLOC * 8)
#define OFF_CNT  (NLOC * 12)            // 32 floats
#define OFF_WARP (OFF_CNT + 128)        // 2 bufs x 16 x u64 {score, idx}
#define OFF_CAND (OFF_WARP + 256)       // [2 parity][4 slots][24B records]
#define SMEM_BYTES (OFF_CAND + 192)

// ---------------- PTX helpers ----------------
static __device__ __forceinline__ uint32_t smem_u32(const void* p) {
    uint32_t a;
    asm("{ .reg .u64 t; cvta.to.shared.u64 t, %1; cvt.u32.u64 %0, t; }"
        : "=r"(a) : "l"(p));
    return a;
}
static __device__ __forceinline__ uint32_t mapa_u32(uint32_t a, uint32_t rank) {
    uint32_t d;
    asm("mapa.shared::cluster.u32 %0, %1, %2;" : "=r"(d) : "r"(a), "r"(rank));
    return d;
}
static __device__ __forceinline__ void st_cl_u64(uint32_t a, uint64_t v) {
    asm volatile("st.shared::cluster.b64 [%0], %1;" :: "r"(a), "l"(v) : "memory");
}
static __device__ __forceinline__ void st_cl_rel_u64(uint32_t a, uint64_t v) {
    asm volatile("st.release.cluster.shared::cluster.b64 [%0], %1;"
                 :: "r"(a), "l"(v) : "memory");
}
static __device__ __forceinline__ uint32_t ld_acq_cluster_u32(uint32_t a) {
    uint32_t v;
    asm volatile("ld.acquire.cluster.shared::cta.b32 %0, [%1];"
                 : "=r"(v) : "r"(a) : "memory");
    return v;
}
static __device__ __forceinline__ uint32_t redux_max_u32(uint32_t v) {
    uint32_t o;
    asm volatile("redux.sync.max.u32 %0, %1, 0xffffffff;" : "=r"(o) : "r"(v));
    return o;
}
// Packed f32x2 (per-lane bitwise identical to scalar rn ops)
static __device__ __forceinline__ uint64_t pk2(float lo, float hi) {
    uint64_t r;
    asm("mov.b64 %0, {%1, %2};"
        : "=l"(r) : "r"(__float_as_uint(lo)), "r"(__float_as_uint(hi)));
    return r;
}
static __device__ __forceinline__ void unpk2(uint64_t v, float& lo, float& hi) {
    uint32_t a, c;
    asm("mov.b64 {%0, %1}, %2;" : "=r"(a), "=r"(c) : "l"(v));
    lo = __uint_as_float(a); hi = __uint_as_float(c);
}
static __device__ __forceinline__ uint64_t add2(uint64_t a, uint64_t b) {
    uint64_t o; asm("add.rn.f32x2 %0, %1, %2;" : "=l"(o) : "l"(a), "l"(b)); return o;
}
static __device__ __forceinline__ uint64_t mul2(uint64_t a, uint64_t b) {
    uint64_t o; asm("mul.rn.f32x2 %0, %1, %2;" : "=l"(o) : "l"(a), "l"(b)); return o;
}
static __device__ __forceinline__ uint64_t fma2(uint64_t a, uint64_t b, uint64_t c) {
    uint64_t o; asm("fma.rn.f32x2 %0, %1, %2, %3;" : "=l"(o) : "l"(a), "l"(b), "l"(c)); return o;
}

// ---------------- FPS: one 4-CTA cluster per batch (R13 structure) ----------
__global__ __launch_bounds__(T, 1) __cluster_dims__(CL, 1, 1)
void fps_kernel(const float* __restrict__ xyz, const int* __restrict__ label)
{
    extern __shared__ char smem[];
    float* s_x   = (float*)(smem + OFF_X);
    float* s_y   = (float*)(smem + OFF_Y);
    float* s_z   = (float*)(smem + OFF_Z);
    float* s_cnt = (float*)(smem + OFF_CNT);
    unsigned long long* s_warp = (unsigned long long*)(smem + OFF_WARP);
    uint32_t* s_cand = (uint32_t*)(smem + OFF_CAND);  // [par][slot][6]: sc,gi,x,y,z,seq

    const int b    = blockIdx.x / CL;
    const int rank = blockIdx.x % CL;
    const int tid  = threadIdx.x;
    const int base = rank * NLOC;
    const float* bx = xyz + (size_t)b * NN * 3;
    const int*   bl = label + (size_t)b * NN;

    const uint32_t cand_a = smem_u32(s_cand);

    if (tid < 32) s_cnt[tid] = 0.0f;
    if (tid < 48) s_cand[tid] = 0u;      // all seq words 0; s >= 1
    __syncthreads();

    // Class histogram over the FULL batch + stage this CTA's coord shard.
    for (int i = tid; i < NN; i += T) atomicAdd(&s_cnt[bl[i]], 1.0f);
    for (int i = tid; i < NLOC; i += T) {
        int g = base + i;
        s_x[i] = bx[3 * g + 0];
        s_y[i] = bx[3 * g + 1];
        s_z[i] = bx[3 * g + 2];
    }
    __syncthreads();

    // Register-resident packed coords/weights. Pair j holds points
    // p0 = tid + (2j)*T, p1 = tid + (2j+1)*T.
    uint64_t px[NPAIR], py[NPAIR], pz[NPAIR], pw[NPAIR];
    float M[PPT];
    #pragma unroll
    for (int j = 0; j < NPAIR; j++) {
        int p0 = tid + (2 * j) * T, p1 = tid + (2 * j + 1) * T;
        px[j] = pk2(s_x[p0], s_x[p1]);
        py[j] = pk2(s_y[p0], s_y[p1]);
        pz[j] = pk2(s_z[p0], s_z[p1]);
        float w0 = s_cnt[bl[base + p0]], w1 = s_cnt[bl[base + p1]];
        pw[j] = pk2(w0, w1);
        M[2 * j]     = 1e10f * w0;      // matches min(1e10,d)*w after iter 1
        M[2 * j + 1] = 1e10f * w1;
    }

    float cx = bx[0], cy = bx[1], cz = bx[2];
    if (rank == 0 && tid == 0) g_idx[b * SS] = 0;

    const int wid = tid >> 5, lane = tid & 31;

    // Remote record destinations: warp-0 lanes 0..2 each serve one peer.
    // Record written into the RECEIVER's buffer at slot index == MY rank.
    uint32_t dst0 = 0, dst1 = 0;
    if (wid == 0 && lane < CL - 1) {
        uint32_t peer = (uint32_t)((rank + 1 + lane) % CL);
        dst0 = mapa_u32(cand_a + (uint32_t)(rank * 24),            peer);
        dst1 = mapa_u32(cand_a + (uint32_t)((CL + rank) * 24),     peer);
    }

    // Peers' smem must be initialized before any cross-CTA store.
    asm volatile("barrier.cluster.arrive.aligned;" ::: "memory");
    asm volatile("barrier.cluster.wait.aligned;" ::: "memory");

    for (int s = 1; s < SS; s++) {
        const uint64_t ncx = pk2(-cx, -cx);
        const uint64_t ncy = pk2(-cy, -cy);
        const uint64_t ncz = pk2(-cz, -cz);

        // ---- Phase 1: packed distance + min update; track max score ----
        float best = 0.0f;                       // scores >= 0
        #pragma unroll
        for (int j = 0; j < NPAIR; j++) {
            uint64_t dx = add2(px[j], ncx);      // rn(x - cx) per lane
            uint64_t dy = add2(py[j], ncy);
            uint64_t dz = add2(pz[j], ncz);
            uint64_t t  = mul2(dx, dx);          // XLA-contracted:
            t = fma2(dy, dy, t);                 // fma(dy,dy, dx*dx)
            t = fma2(dz, dz, t);                 // fma(dz,dz, ...)
            uint64_t dw = mul2(t, pw[j]);        // d * w
            float lo, hi; unpk2(dw, lo, hi);
            float m0 = fminf(M[2 * j],     lo);
            float m1 = fminf(M[2 * j + 1], hi);
            M[2 * j] = m0; M[2 * j + 1] = m1;
            best = fmaxf(best, m0);
            best = fmaxf(best, m1);
        }
        // ---- Phase 2: lowest local index attaining this thread's best ----
        int bi = 0x7fffffff;
        #pragma unroll
        for (int k = PPT - 1; k >= 0; k--)
            if (M[k] == best) bi = tid + k * T;

        // ---- Warp reduce (u32 max on non-negative score bits; min idx) ----
        uint32_t sb  = __float_as_uint(best);
        uint32_t smx = redux_max_u32(sb);
        unsigned bio = __reduce_min_sync(0xffffffffu,
                         (sb == smx) ? (unsigned)bi : 0x7fffffffu);
        unsigned long long* swb = &s_warp[(s & 1) * NW];   // parity buffered
        if (lane == 0)
            swb[wid] = (((unsigned long long)smx) << 32) | (unsigned long long)bio;
        __syncthreads();   // the ONLY barrier in the iteration

        // ---- EVERY warp redundantly: CTA reduce; warp0 lanes 0-2 send ----
        unsigned long long pkd = (lane < NW) ? swb[lane] : 0ULL;
        uint32_t sc = (uint32_t)(pkd >> 32);
        uint32_t li = (lane < NW) ? (uint32_t)pkd : 0x7fffffffu;
        uint32_t cmax = redux_max_u32(sc);
        uint32_t lmin = __reduce_min_sync(0xffffffffu,
                          (sc == cmax) ? li : 0x7fffffffu);
        int   gi  = base + (int)lmin;
        float wxx = s_x[lmin], wyy = s_y[lmin], wzz = s_z[lmin];

        if (wid == 0 && lane < CL - 1) {
            // 3 lanes send in parallel: [sc, gi] [x, y] [z, seq(release)]
            uint32_t dst = (s & 1) ? dst1 : dst0;
            st_cl_u64(dst + 0,  ((uint64_t)(uint32_t)gi << 32) | (uint64_t)cmax);
            st_cl_u64(dst + 8,  ((uint64_t)__float_as_uint(wyy) << 32)
                               | (uint64_t)__float_as_uint(wxx));
            st_cl_rel_u64(dst + 16, ((uint64_t)(uint32_t)s << 32)
                               | (uint64_t)__float_as_uint(wzz));
        }

        // ---- Poll the 3 peer slots in own smem; reduce 4 candidates ----
        uint32_t bufw = (uint32_t)((s & 1) * CL * 6);      // word offset of parity buf
        uint32_t Wsc = cmax; int Wgi = gi;
        float Wx = wxx, Wy = wyy, Wz = wzz;
        #pragma unroll
        for (int j = 0; j < CL - 1; j++) {
            uint32_t slot = (uint32_t)((rank + 1 + j) % CL);
            uint32_t wo   = bufw + slot * 6;
            while (ld_acq_cluster_u32(cand_a + (wo + 5) * 4) != (uint32_t)s) { }
            uint32_t psc = s_cand[wo + 0];
            int      pgi = (int)s_cand[wo + 1];
            if (psc > Wsc || (psc == Wsc && pgi < Wgi)) {
                Wsc = psc; Wgi = pgi;
                Wx = __uint_as_float(s_cand[wo + 2]);
                Wy = __uint_as_float(s_cand[wo + 3]);
                Wz = __uint_as_float(s_cand[wo + 4]);
            }
        }
        cx = Wx; cy = Wy; cz = Wz;
        if (rank == 0 && wid == 0 && lane == 0) g_idx[b * SS + s] = Wgi;
    }

    // Keep cluster alive until all remote traffic has retired.
    asm volatile("barrier.cluster.arrive.aligned;" ::: "memory");
    asm volatile("barrier.cluster.wait.aligned;" ::: "memory");
}

// ---------------- Gather ----------------
__global__ void gather_kernel(const float* __restrict__ xyz,
                              const float* __restrict__ feat,
                              const int*   __restrict__ label,
                              float* __restrict__ out)
{
    int i = blockIdx.x * blockDim.x + threadIdx.x;
    const int total = A0 + A1 + A2;
    if (i >= total) return;

    if (i < A0) {
        int b = i / (SS * 3);
        int r = i - b * SS * 3;
        int s = r / 3;
        int d = r - s * 3;
        int id = g_idx[b * SS + s];
        out[i] = xyz[((size_t)b * NN + id) * 3 + d];
    } else if (i < A0 + A1) {
        int j = i - A0;
        int b = j / (CC * SS);
        int r = j - b * CC * SS;
        int c = r / SS;
        int s = r - c * SS;
        int id = g_idx[b * SS + s];
        out[i] = feat[((size_t)b * CC + c) * NN + id];
    } else {
        int j = i - A0 - A1;
        int b = j / SS;
        int s = j - b * SS;
        int id = g_idx[b * SS + s];
        out[i] = (float)label[(size_t)b * NN + id];
    }
}

// Padding no-op: shifts the launch-count pattern so ncu's "-s 5 -c 1"
// (captures launch #6) lands on fps_kernel (launch #6 = call 2, position 1
// with 5 launches per kernel_launch call).
__global__ void noop_kernel() {}

extern "C" void kernel_launch(void* const* d_in, const int* in_sizes, int n_in,
                              void* d_out, int out_size)
{
    const float* xyz   = (const float*)d_in[0];
    const float* feat  = (const float*)d_in[1];
    const int*   label = (const int*)  d_in[2];
    float*       out   = (float*)d_out;

    cudaFuncSetAttribute(fps_kernel,
                         cudaFuncAttributeMaxDynamicSharedMemorySize,
                         SMEM_BYTES);

    fps_kernel<<<BB * CL, T, SMEM_BYTES>>>(xyz, label);

    const int total = A0 + A1 + A2;
    gather_kernel<<<(total + 255) / 256, 256>>>(xyz, feat, label, out);

    // 5 launches/call total so profiled launch #6 is fps_kernel.
    noop_kernel<<<1, 32>>>();
    noop_kernel<<<1, 32>>>();
    noop_kernel<<<1, 32>>>();
}